// round 8
// baseline (speedup 1.0000x reference)
#include <cuda_runtime.h>
#include <cstdint>

// IntensityTransformation: out_k[b,c,h,w] = tf_k[b,c, round(255*img[b,c,h,w])]
// B=8, C=3, H=W=1024, LUT=256. Output = concat(out1, out2, out3), fp32.
//
// R7: TMA 1D bulk stores. Outputs are staged in smem (double-buffered) and
// drained with cp.async.bulk in 8KB contiguous bursts per output stream:
//   - long row-sequential DRAM write runs instead of interleaved 512B chunks
//   - zero STG wavefronts through L1TEX (smem -> L2 direct)
// LUT is x8-replicated in smem for near-conflict-free LDS.32.

static constexpr int PLANES = 24;                    // B*C
static constexpr long long PLANE = 1024LL * 1024LL;  // floats per plane
static constexpr int LUT = 256;
static constexpr int REP = 8;                        // LUT replication
static constexpr int TILE_F4 = 512;                  // float4 per tile (8KB per output)
static constexpr int TILE_BYTES = TILE_F4 * 16;      // 8192
static constexpr int TILES_PER_PLANE = (int)(PLANE / 4 / TILE_F4);  // 512

static constexpr int LUT_FLOATS = 3 * LUT * REP;     // 6144 floats = 24KB
// smem: 24KB LUT + 2 stages * 3 outputs * 8KB = 72KB
static constexpr int SMEM_BYTES = LUT_FLOATS * 4 + 2 * 3 * TILE_BYTES;  // 73728

__device__ __forceinline__ uint32_t smem_u32(const void* p) {
    uint32_t a;
    asm("{ .reg .u64 t; cvta.to.shared.u64 t, %1; cvt.u32.u64 %0, t; }"
        : "=r"(a) : "l"(p));
    return a;
}

__device__ __forceinline__ void bulk_store(void* gdst, uint32_t ssrc, int bytes) {
    asm volatile("cp.async.bulk.global.shared::cta.bulk_group [%0], [%1], %2;"
                 :: "l"(gdst), "r"(ssrc), "r"(bytes) : "memory");
}

__global__ __launch_bounds__(256)
void intensity_lut_tma_kernel(const float* __restrict__ img,
                              const float* __restrict__ tf1,
                              const float* __restrict__ tf2,
                              const float* __restrict__ tf3,
                              float* __restrict__ out)
{
    extern __shared__ float smem[];
    float* lut = smem;                                   // [3][256][8]
    float4* staging = (float4*)(smem + LUT_FLOATS);      // [2][3][512]

    const int plane = blockIdx.y;   // 0..23
    const int t = threadIdx.x;      // 0..255
    const int r = t & (REP - 1);    // this thread's LUT replica

    // Fill x8-replicated LUT (entry t, rotated slots to avoid fill conflicts).
    {
        const float v1 = tf1[plane * LUT + t];
        const float v2 = tf2[plane * LUT + t];
        const float v3 = tf3[plane * LUT + t];
#pragma unroll
        for (int i = 0; i < REP; i++) {
            const int slot = (i + t) & (REP - 1);
            lut[t * REP + slot]               = v1;
            lut[(LUT + t) * REP + slot]       = v2;
            lut[(2 * LUT + t) * REP + slot]   = v3;
        }
    }
    __syncthreads();

    const float4* __restrict__ in4 =
        reinterpret_cast<const float4*>(img) + (long long)plane * (PLANE / 4);

    // Byte base of this plane inside each output stream.
    char* const ob = reinterpret_cast<char*>(out);
    char* const o1 = ob + (long long)(0 * PLANES + plane) * PLANE * 4;
    char* const o2 = ob + (long long)(1 * PLANES + plane) * PLANE * 4;
    char* const o3 = ob + (long long)(2 * PLANES + plane) * PLANE * 4;

    int stage = 0;
    for (int tile = blockIdx.x; tile < TILES_PER_PLANE; tile += gridDim.x) {
        const long long e0 = (long long)tile * TILE_F4;

        // Front-batched global loads (overlap with TMA drain of prior tile).
        const float4 va = __ldcs(&in4[e0 + t]);
        const float4 vb = __ldcs(&in4[e0 + 256 + t]);

        const int a0 = __float2int_rn(255.0f * va.x) * REP + r;
        const int a1 = __float2int_rn(255.0f * va.y) * REP + r;
        const int a2 = __float2int_rn(255.0f * va.z) * REP + r;
        const int a3 = __float2int_rn(255.0f * va.w) * REP + r;
        const int b0 = __float2int_rn(255.0f * vb.x) * REP + r;
        const int b1 = __float2int_rn(255.0f * vb.y) * REP + r;
        const int b2 = __float2int_rn(255.0f * vb.z) * REP + r;
        const int b3 = __float2int_rn(255.0f * vb.w) * REP + r;

        const float* l1 = lut;
        const float* l2 = lut + LUT * REP;
        const float* l3 = lut + 2 * LUT * REP;

        const float4 ra1 = make_float4(l1[a0], l1[a1], l1[a2], l1[a3]);
        const float4 ra2 = make_float4(l2[a0], l2[a1], l2[a2], l2[a3]);
        const float4 ra3 = make_float4(l3[a0], l3[a1], l3[a2], l3[a3]);
        const float4 rb1 = make_float4(l1[b0], l1[b1], l1[b2], l1[b3]);
        const float4 rb2 = make_float4(l2[b0], l2[b1], l2[b2], l2[b3]);
        const float4 rb3 = make_float4(l3[b0], l3[b1], l3[b2], l3[b3]);

        // Make sure the bulk-group that last read this stage buffer (issued
        // two iterations ago) has finished reading smem.
        if (t == 0) {
            asm volatile("cp.async.bulk.wait_group.read 1;" ::: "memory");
        }
        __syncthreads();

        float4* buf = staging + stage * 3 * TILE_F4;
        buf[0 * TILE_F4 + t]       = ra1;
        buf[0 * TILE_F4 + 256 + t] = rb1;
        buf[1 * TILE_F4 + t]       = ra2;
        buf[1 * TILE_F4 + 256 + t] = rb2;
        buf[2 * TILE_F4 + t]       = ra3;
        buf[2 * TILE_F4 + 256 + t] = rb3;

        // Order generic smem stores before async-proxy (TMA) reads.
        asm volatile("fence.proxy.async.shared::cta;" ::: "memory");
        __syncthreads();

        if (t == 0) {
            const long long off = (long long)tile * TILE_BYTES;
            bulk_store(o1 + off, smem_u32(buf + 0 * TILE_F4), TILE_BYTES);
            bulk_store(o2 + off, smem_u32(buf + 1 * TILE_F4), TILE_BYTES);
            bulk_store(o3 + off, smem_u32(buf + 2 * TILE_F4), TILE_BYTES);
            asm volatile("cp.async.bulk.commit_group;" ::: "memory");
        }
        stage ^= 1;
    }

    // Drain all outstanding bulk stores before exit.
    if (t == 0) {
        asm volatile("cp.async.bulk.wait_group 0;" ::: "memory");
    }
}

extern "C" void kernel_launch(void* const* d_in, const int* in_sizes, int n_in,
                              void* d_out, int out_size)
{
    const float* img = (const float*)d_in[0];
    const float* tf1 = (const float*)d_in[1];
    const float* tf2 = (const float*)d_in[2];
    const float* tf3 = (const float*)d_in[3];
    float* out = (float*)d_out;

    cudaFuncSetAttribute(intensity_lut_tma_kernel,
                         cudaFuncAttributeMaxDynamicSharedMemorySize, SMEM_BYTES);

    // 18 x 24 = 432 CTAs; 72KB smem -> 3 CTAs/SM, ~all resident in one wave.
    dim3 grid(18, PLANES);
    dim3 block(256);
    intensity_lut_tma_kernel<<<grid, block, SMEM_BYTES>>>(img, tf1, tf2, tf3, out);
}

// round 10
// speedup vs baseline: 1.0751x; 1.0751x over previous
#include <cuda_runtime.h>
#include <cstdint>

// IntensityTransformation: out_k[b,c,h,w] = tf_k[b,c, round(255*img[b,c,h,w])]
// B=8, C=3, H=W=1024, LUT=256. Output = concat(out1, out2, out3), fp32.
//
// R9: back to the R5 high-occupancy streaming shape, but with Blackwell
// 256-bit global loads/stores (ld/st.global.v8.f32). Per 8 pixels:
// 1 LDG.256 + 3 STG.256 (was 2 LDG.128 + 6 STG.128) -> half the LSU issue
// train, double the bytes in flight per slot. LUT = float4[256] in smem
// (one LDS.128 fetches all three outputs' values for a pixel).

static constexpr int PLANES = 24;                    // B*C
static constexpr long long PLANE = 1024LL * 1024LL;  // floats per plane
static constexpr int LUT = 256;

__device__ __forceinline__ void ldg256(const float* p, float v[8]) {
    asm volatile("ld.global.nc.v8.f32 {%0,%1,%2,%3,%4,%5,%6,%7}, [%8];"
                 : "=f"(v[0]), "=f"(v[1]), "=f"(v[2]), "=f"(v[3]),
                   "=f"(v[4]), "=f"(v[5]), "=f"(v[6]), "=f"(v[7])
                 : "l"(p));
}

__device__ __forceinline__ void stg256(float* p, const float v[8]) {
    asm volatile("st.global.v8.f32 [%0], {%1,%2,%3,%4,%5,%6,%7,%8};"
                 :: "l"(p),
                    "f"(v[0]), "f"(v[1]), "f"(v[2]), "f"(v[3]),
                    "f"(v[4]), "f"(v[5]), "f"(v[6]), "f"(v[7])
                 : "memory");
}

__global__ __launch_bounds__(256)
void intensity_lut_v8_kernel(const float* __restrict__ img,
                             const float* __restrict__ tf1,
                             const float* __restrict__ tf2,
                             const float* __restrict__ tf3,
                             float* __restrict__ out)
{
    __shared__ float4 slut[LUT];   // {tf1[i], tf2[i], tf3[i], 0}

    const int plane = blockIdx.y;  // 0..23
    const int t = threadIdx.x;     // blockDim.x == 256

    slut[t] = make_float4(tf1[plane * LUT + t],
                          tf2[plane * LUT + t],
                          tf3[plane * LUT + t],
                          0.0f);
    __syncthreads();

    const long long base = (long long)plane * PLANE;
    const float* __restrict__ in = img + base;
    float* __restrict__ o1 = out + base;
    float* __restrict__ o2 = out + (long long)PLANES * PLANE + base;
    float* __restrict__ o3 = out + 2LL * PLANES * PLANE + base;

    const int n8 = (int)(PLANE / 8);          // 131072 groups of 8 per plane
    const int stride = gridDim.x * blockDim.x;

    for (int i = blockIdx.x * blockDim.x + t; i < n8; i += stride) {
        const long long e = (long long)i * 8;

        float v[8];
        ldg256(in + e, v);

        int ix[8];
#pragma unroll
        for (int k = 0; k < 8; k++)
            ix[k] = __float2int_rn(255.0f * v[k]);

        float r1[8], r2[8], r3[8];
#pragma unroll
        for (int k = 0; k < 8; k++) {
            float4 l = slut[ix[k]];
            r1[k] = l.x;
            r2[k] = l.y;
            r3[k] = l.z;
        }

        stg256(o1 + e, r1);
        stg256(o2 + e, r2);
        stg256(o3 + e, r3);
    }
}

extern "C" void kernel_launch(void* const* d_in, const int* in_sizes, int n_in,
                              void* d_out, int out_size)
{
    const float* img = (const float*)d_in[0];
    const float* tf1 = (const float*)d_in[1];
    const float* tf2 = (const float*)d_in[2];
    const float* tf3 = (const float*)d_in[3];
    float* out = (float*)d_out;

    // 128 x 24 = 3072 CTAs; each thread does 4 groups of 8 -> loop reuse,
    // high occupancy (small smem/regs), plenty of independent LDG.256 in flight.
    dim3 grid(128, PLANES);
    dim3 block(256);
    intensity_lut_v8_kernel<<<grid, block>>>(img, tf1, tf2, tf3, out);
}